// round 1
// baseline (speedup 1.0000x reference)
#include <cuda_runtime.h>

#define NB   8
#define CIN  64
#define COUT 128
#define HH   32
#define WW   32
#define HP   34
#define WP   34
#define NCH  16   // CIN / 4 packed int8 chunks

// ---------------- scratch (device globals; no allocation) ----------------
__device__ unsigned g_max2[2];                  // max|x| bits, max|w| bits
__device__ float    g_sc[3];                    // 127/Tf, 127/Tw, (Tf/127)*(Tw/127)
__device__ int      g_xpack[NB*HP*WP*NCH];      // padded NHWC, ci packed 4/int32
__device__ int      g_wpack[COUT*9*NCH];        // [co][tap][chunk]

// ---------------- kernels ----------------
__global__ void k_init() {
    g_max2[0] = 0u;
    g_max2[1] = 0u;
}

__global__ void k_reduce(const float* __restrict__ x, const float* __restrict__ w) {
    const int which = blockIdx.y;
    const float* p = which ? w : x;
    const int n = which ? (COUT*CIN*9) : (NB*CIN*HH*WW);
    unsigned m = 0u;
    for (int i = blockIdx.x*blockDim.x + threadIdx.x; i < n; i += gridDim.x*blockDim.x)
        m = max(m, __float_as_uint(fabsf(p[i])));
    #pragma unroll
    for (int o = 16; o; o >>= 1) m = max(m, __shfl_xor_sync(0xffffffffu, m, o));
    __shared__ unsigned sred[8];
    if ((threadIdx.x & 31) == 0) sred[threadIdx.x >> 5] = m;
    __syncthreads();
    if (threadIdx.x < 32) {
        m = (threadIdx.x < (blockDim.x >> 5)) ? sred[threadIdx.x] : 0u;
        #pragma unroll
        for (int o = 4; o; o >>= 1) m = max(m, __shfl_xor_sync(0xffffffffu, m, o));
        if (threadIdx.x == 0) atomicMax(&g_max2[which], m);
    }
}

// scalar EMA thresholds + scales; forced non-contracted fp32 to match JAX bit-exact
__global__ void k_scalars(const float* __restrict__ Tf_in, const float* __restrict__ Tw_in) {
    float mx = __uint_as_float(g_max2[0]);
    float mw = __uint_as_float(g_max2[1]);
    float Tf = __fadd_rn(__fmul_rn(0.95f, Tf_in[0]), __fmul_rn(0.05f, mx));
    float Tw = __fadd_rn(__fmul_rn(0.95f, Tw_in[0]), __fmul_rn(0.05f, mw));
    g_sc[0] = __fdiv_rn(127.0f, Tf);
    g_sc[1] = __fdiv_rn(127.0f, Tw);
    g_sc[2] = __fmul_rn(__fdiv_rn(Tf, 127.0f), __fdiv_rn(Tw, 127.0f));
}

__device__ __forceinline__ int quant(float v, float s) {
    float r = rintf(__fmul_rn(v, s));          // rintf == round half-to-even == jnp.round
    r = fminf(fmaxf(r, -128.0f), 127.0f);
    return (int)r;
}

// quantize + pack x into padded [b][r][c][chunk] int32 (4 x int8), zero border
__global__ void k_qx(const float* __restrict__ x) {
    int i = blockIdx.x*blockDim.x + threadIdx.x;
    if (i >= NB*HP*WP*NCH) return;
    int ch = i & (NCH - 1);
    int t  = i >> 4;
    int c  = t % WP; t /= WP;
    int r  = t % HP;
    int b  = t / HP;
    int v = 0;
    if (r >= 1 && r <= HH && c >= 1 && c <= WW) {
        float s = g_sc[0];
        const float* px = x + (((b*CIN + ch*4)*HH) + (r - 1))*WW + (c - 1);
        int q0 = quant(px[0*HH*WW], s) & 255;
        int q1 = quant(px[1*HH*WW], s) & 255;
        int q2 = quant(px[2*HH*WW], s) & 255;
        int q3 = quant(px[3*HH*WW], s) & 255;
        v = q0 | (q1 << 8) | (q2 << 16) | (q3 << 24);
    }
    g_xpack[i] = v;
}

// quantize + pack weight into [co][tap][chunk] int32
__global__ void k_qw(const float* __restrict__ w) {
    int i = blockIdx.x*blockDim.x + threadIdx.x;
    if (i >= COUT*9*NCH) return;
    int ch  = i & (NCH - 1);
    int t   = i >> 4;
    int tap = t % 9;
    int co  = t / 9;
    float s = g_sc[1];
    const float* pw = w + (co*CIN + ch*4)*9 + tap;   // stride 9 between ci
    int q0 = quant(pw[0],  s) & 255;
    int q1 = quant(pw[9],  s) & 255;
    int q2 = quant(pw[18], s) & 255;
    int q3 = quant(pw[27], s) & 255;
    g_wpack[i] = q0 | (q1 << 8) | (q2 << 16) | (q3 << 24);
}

// conv: one block per (b, y); 256 threads; thread = 4 cols (stride 8) x 4 couts
__global__ void __launch_bounds__(256, 2)
k_conv(const float* __restrict__ bias, float* __restrict__ out) {
    extern __shared__ int4 smem[];
    int4* ws4 = smem;                   // [co][tap][c4]   : 128*9*4 = 4608 int4 (72KB)
    int4* xs4 = smem + COUT*9*4;        // [dy][c4][col]   : 3*4*34  = 408 int4

    const int b = blockIdx.x >> 5;
    const int y = blockIdx.x & 31;
    const int t = threadIdx.x;

    const int4* wp4 = (const int4*)g_wpack;
    #pragma unroll
    for (int i = t; i < COUT*9*4; i += 256) ws4[i] = wp4[i];

    const int4* xp4 = (const int4*)g_xpack;   // 4 int4 per (b,r,c)
    for (int i = t; i < 3*4*WP; i += 256) {
        int col = i % WP;
        int q   = i / WP;       // dy*4 + c4
        int c4  = q & 3;
        int dy  = q >> 2;
        xs4[(dy*4 + c4)*WP + col] = xp4[((b*HP + (y + dy))*WP + col)*4 + c4];
    }
    __syncthreads();

    const int cog  = t >> 3;    // 0..31
    const int colg = t & 7;     // 0..7 -> cols colg + {0,8,16,24}
    const int co0  = cog * 4;

    int acc[4][4];
    #pragma unroll
    for (int m = 0; m < 4; ++m)
        #pragma unroll
        for (int q = 0; q < 4; ++q) acc[m][q] = 0;

    #pragma unroll 1
    for (int ky = 0; ky < 3; ++ky) {
        #pragma unroll 1
        for (int kx = 0; kx < 3; ++kx) {
            const int tap = ky*3 + kx;
            #pragma unroll
            for (int c4 = 0; c4 < 4; ++c4) {
                int4 wv[4], xv[4];
                #pragma unroll
                for (int q = 0; q < 4; ++q)
                    wv[q] = ws4[(co0 + q)*36 + tap*4 + c4];
                #pragma unroll
                for (int m = 0; m < 4; ++m)
                    xv[m] = xs4[(ky*4 + c4)*WP + colg + 8*m + kx];
                #pragma unroll
                for (int m = 0; m < 4; ++m)
                    #pragma unroll
                    for (int q = 0; q < 4; ++q) {
                        acc[m][q] = __dp4a(xv[m].x, wv[q].x, acc[m][q]);
                        acc[m][q] = __dp4a(xv[m].y, wv[q].y, acc[m][q]);
                        acc[m][q] = __dp4a(xv[m].z, wv[q].z, acc[m][q]);
                        acc[m][q] = __dp4a(xv[m].w, wv[q].w, acc[m][q]);
                    }
            }
        }
    }

    const float s = g_sc[2];
    #pragma unroll
    for (int q = 0; q < 4; ++q) {
        const int co = co0 + q;
        const float bq = __ldg(&bias[co]);
        float* po = out + ((b*COUT + co)*HH + y)*WW;
        #pragma unroll
        for (int m = 0; m < 4; ++m)
            po[colg + 8*m] = (float)acc[m][q] * s + bq;
    }
}

// ---------------- launch ----------------
extern "C" void kernel_launch(void* const* d_in, const int* in_sizes, int n_in,
                              void* d_out, int out_size) {
    const float* x    = (const float*)d_in[0];
    const float* w    = (const float*)d_in[1];
    const float* bias = (const float*)d_in[2];
    // d_in[3] = lut (exact a*b table -> replaced by dp4a), d_in[4] = gradient_lut (unused)
    const float* Tf   = (const float*)d_in[5];
    const float* Tw   = (const float*)d_in[6];
    float* out = (float*)d_out;

    k_init<<<1, 32>>>();
    dim3 rg(96, 2);
    k_reduce<<<rg, 256>>>(x, w);
    k_scalars<<<1, 1>>>(Tf, Tw);
    k_qx<<<(NB*HP*WP*NCH + 255)/256, 256>>>(x);
    k_qw<<<(COUT*9*NCH + 255)/256, 256>>>(w);

    const int SMEM = (COUT*9*4 + 3*4*WP) * (int)sizeof(int4);   // 80256 B
    cudaFuncSetAttribute(k_conv, cudaFuncAttributeMaxDynamicSharedMemorySize, SMEM);
    k_conv<<<NB*HH, 256, SMEM>>>(bias, out);
}

// round 2
// speedup vs baseline: 1.3735x; 1.3735x over previous
#include <cuda_runtime.h>

#define NB   8
#define CIN  64
#define COUT 128
#define HH   32
#define WW   32
#define HP   34
#define WP   34
#define NCH  16          // CIN/4 int8-packed chunks
#define RXB  96          // reduce blocks for x
#define RWB  16          // reduce blocks for w
#define QXN  (NB*HP*4*WP)        // 36992 int4 elements of packed x
#define QXB  ((QXN + 255) / 256) // 145 blocks
#define QWB  ((COUT*9*NCH) / 256)// 72 blocks

// ---------------- scratch (device globals; no allocation) ----------------
__device__ unsigned g_part[RXB + RWB];          // per-block |max| partials (bits)
__device__ float    g_sc[3];                    // 127/Tf, 127/Tw, (Tf/127)*(Tw/127)
__device__ int4     g_xpack4[QXN];              // [b][r][c4][col], int4 = 4 chunks (16 ch)
__device__ int      g_wpack[COUT*9*NCH];        // [co][tap][chunk]

// ---------------- reduce: per-block partial max|.| ----------------
__global__ void k_reduce(const float4* __restrict__ x, const float4* __restrict__ w) {
    const bool isw = blockIdx.x >= RXB;
    const float4* p = isw ? w : x;
    const int n   = isw ? (COUT*CIN*9/4) : (NB*CIN*HH*WW/4);
    const int bid = isw ? (blockIdx.x - RXB) : blockIdx.x;
    const int nb  = isw ? RWB : RXB;
    unsigned m = 0u;
    for (int i = bid*blockDim.x + threadIdx.x; i < n; i += nb*blockDim.x) {
        float4 v = p[i];
        m = max(m, __float_as_uint(fabsf(v.x)));
        m = max(m, __float_as_uint(fabsf(v.y)));
        m = max(m, __float_as_uint(fabsf(v.z)));
        m = max(m, __float_as_uint(fabsf(v.w)));
    }
    #pragma unroll
    for (int o = 16; o; o >>= 1) m = max(m, __shfl_xor_sync(0xffffffffu, m, o));
    __shared__ unsigned sred[8];
    if ((threadIdx.x & 31) == 0) sred[threadIdx.x >> 5] = m;
    __syncthreads();
    if (threadIdx.x < 32) {
        m = (threadIdx.x < (blockDim.x >> 5)) ? sred[threadIdx.x] : 0u;
        #pragma unroll
        for (int o = 4; o; o >>= 1) m = max(m, __shfl_xor_sync(0xffffffffu, m, o));
        if (threadIdx.x == 0) g_part[blockIdx.x] = m;
    }
}

// ---------------- final reduce + scalar EMA thresholds/scales ----------------
__global__ void k_scalars(const float* __restrict__ Tf_in, const float* __restrict__ Tw_in) {
    const int t = threadIdx.x;   // 128 threads
    unsigned vx = (t < RXB) ? g_part[t] : 0u;
    unsigned vw = (t < RWB) ? g_part[RXB + t] : 0u;
    #pragma unroll
    for (int o = 16; o; o >>= 1) {
        vx = max(vx, __shfl_xor_sync(0xffffffffu, vx, o));
        vw = max(vw, __shfl_xor_sync(0xffffffffu, vw, o));
    }
    __shared__ unsigned sx[4], sw_[4];
    if ((t & 31) == 0) { sx[t >> 5] = vx; sw_[t >> 5] = vw; }
    __syncthreads();
    if (t == 0) {
        unsigned mx = 0u, mw = 0u;
        #pragma unroll
        for (int i = 0; i < 4; ++i) { mx = max(mx, sx[i]); mw = max(mw, sw_[i]); }
        float Tf = __fadd_rn(__fmul_rn(0.95f, Tf_in[0]), __fmul_rn(0.05f, __uint_as_float(mx)));
        float Tw = __fadd_rn(__fmul_rn(0.95f, Tw_in[0]), __fmul_rn(0.05f, __uint_as_float(mw)));
        g_sc[0] = __fdiv_rn(127.0f, Tf);
        g_sc[1] = __fdiv_rn(127.0f, Tw);
        g_sc[2] = __fmul_rn(__fdiv_rn(Tf, 127.0f), __fdiv_rn(Tw, 127.0f));
    }
}

__device__ __forceinline__ int quant(float v, float s) {
    float r = rintf(__fmul_rn(v, s));            // rintf == round half-to-even == jnp.round
    r = fminf(fmaxf(r, -128.0f), 127.0f);
    return (int)r;
}

// ---------------- fused quantize+pack for x and w ----------------
__global__ void k_pack(const float* __restrict__ x, const float* __restrict__ w) {
    if (blockIdx.x < QXB) {
        // ---- x: one int4 (16 channels of one padded pixel) per thread, coalesced ----
        int i = blockIdx.x*256 + threadIdx.x;
        if (i >= QXN) return;
        int col = i % WP;
        int t2  = i / WP;
        int c4  = t2 & 3; t2 >>= 2;
        int r   = t2 % HP;
        int b   = t2 / HP;
        int4 v = make_int4(0, 0, 0, 0);
        if (r >= 1 && r <= HH && col >= 1 && col <= WW) {
            const float s = g_sc[0];
            const float* px = x + (((b*CIN + c4*16)*HH) + (r - 1))*WW + (col - 1);
            int q[16];
            #pragma unroll
            for (int j = 0; j < 16; ++j)
                q[j] = quant(px[j*HH*WW], s) & 255;
            v.x = q[0]  | (q[1]  << 8) | (q[2]  << 16) | (q[3]  << 24);
            v.y = q[4]  | (q[5]  << 8) | (q[6]  << 16) | (q[7]  << 24);
            v.z = q[8]  | (q[9]  << 8) | (q[10] << 16) | (q[11] << 24);
            v.w = q[12] | (q[13] << 8) | (q[14] << 16) | (q[15] << 24);
        }
        g_xpack4[i] = v;
    } else {
        // ---- w: one int32 chunk per thread ----
        int i = (blockIdx.x - QXB)*256 + threadIdx.x;   // < 18432 exactly
        int ch  = i & (NCH - 1);
        int t2  = i >> 4;
        int tap = t2 % 9;
        int co  = t2 / 9;
        const float s = g_sc[1];
        const float* pw = w + (co*CIN + ch*4)*9 + tap;  // stride 9 between ci
        int q0 = quant(pw[0],  s) & 255;
        int q1 = quant(pw[9],  s) & 255;
        int q2 = quant(pw[18], s) & 255;
        int q3 = quant(pw[27], s) & 255;
        g_wpack[i] = q0 | (q1 << 8) | (q2 << 16) | (q3 << 24);
    }
}

// ---------------- conv: 128 blocks (one wave), block = (b, 2 rows) ----------------
// thread = 4 cols (stride 8) x 4 couts x 2 rows
__global__ void __launch_bounds__(256, 1)
k_conv(const float* __restrict__ bias, float* __restrict__ out) {
    extern __shared__ int4 smem[];
    int4* ws4 = smem;                   // [co][tap][c4] : 4608 int4 (72KB)
    int4* xs4 = smem + COUT*9*4;        // [dy][c4][col] : 4*4*34 = 544 int4

    const int b  = blockIdx.x >> 4;
    const int y0 = (blockIdx.x & 15) * 2;
    const int t  = threadIdx.x;

    const int4* wp4 = (const int4*)g_wpack;
    #pragma unroll
    for (int i = t; i < COUT*9*4; i += 256) ws4[i] = wp4[i];

    // x rows y0..y0+3, contiguous in the new layout
    const int4* xsrc = g_xpack4 + (b*HP + y0)*4*WP;
    #pragma unroll
    for (int i = t; i < 4*4*WP; i += 256) xs4[i] = xsrc[i];
    __syncthreads();

    const int cog  = t >> 3;    // 0..31
    const int colg = t & 7;     // cols colg + {0,8,16,24}
    const int co0  = cog * 4;

    int acc[2][4][4];
    #pragma unroll
    for (int r2 = 0; r2 < 2; ++r2)
        #pragma unroll
        for (int m = 0; m < 4; ++m)
            #pragma unroll
            for (int q = 0; q < 4; ++q) acc[r2][m][q] = 0;

    #pragma unroll 1
    for (int ky = 0; ky < 3; ++ky) {
        #pragma unroll 1
        for (int kx = 0; kx < 3; ++kx) {
            const int tap = ky*3 + kx;
            #pragma unroll
            for (int c4 = 0; c4 < 4; ++c4) {
                int4 wv[4];
                #pragma unroll
                for (int q = 0; q < 4; ++q)
                    wv[q] = ws4[(co0 + q)*36 + tap*4 + c4];
                #pragma unroll
                for (int r2 = 0; r2 < 2; ++r2) {
                    int4 xv[4];
                    #pragma unroll
                    for (int m = 0; m < 4; ++m)
                        xv[m] = xs4[((r2 + ky)*4 + c4)*WP + colg + 8*m + kx];
                    #pragma unroll
                    for (int m = 0; m < 4; ++m)
                        #pragma unroll
                        for (int q = 0; q < 4; ++q) {
                            acc[r2][m][q] = __dp4a(xv[m].x, wv[q].x, acc[r2][m][q]);
                            acc[r2][m][q] = __dp4a(xv[m].y, wv[q].y, acc[r2][m][q]);
                            acc[r2][m][q] = __dp4a(xv[m].z, wv[q].z, acc[r2][m][q]);
                            acc[r2][m][q] = __dp4a(xv[m].w, wv[q].w, acc[r2][m][q]);
                        }
                }
            }
        }
    }

    const float s = g_sc[2];
    #pragma unroll
    for (int q = 0; q < 4; ++q) {
        const int co = co0 + q;
        const float bq = __ldg(&bias[co]);
        #pragma unroll
        for (int r2 = 0; r2 < 2; ++r2) {
            float* po = out + ((b*COUT + co)*HH + (y0 + r2))*WW;
            #pragma unroll
            for (int m = 0; m < 4; ++m)
                po[colg + 8*m] = (float)acc[r2][m][q] * s + bq;
        }
    }
}

// ---------------- launch ----------------
extern "C" void kernel_launch(void* const* d_in, const int* in_sizes, int n_in,
                              void* d_out, int out_size) {
    const float* x    = (const float*)d_in[0];
    const float* w    = (const float*)d_in[1];
    const float* bias = (const float*)d_in[2];
    // d_in[3] = lut (exact a*b -> dp4a), d_in[4] = gradient_lut (unused)
    const float* Tf   = (const float*)d_in[5];
    const float* Tw   = (const float*)d_in[6];
    float* out = (float*)d_out;

    k_reduce<<<RXB + RWB, 256>>>((const float4*)x, (const float4*)w);
    k_scalars<<<1, 128>>>(Tf, Tw);
    k_pack<<<QXB + QWB, 256>>>(x, w);

    const int SMEM = (COUT*9*4 + 4*4*WP) * (int)sizeof(int4);   // 82432 B
    cudaFuncSetAttribute(k_conv, cudaFuncAttributeMaxDynamicSharedMemorySize, SMEM);
    k_conv<<<NB*HH/2, 256, SMEM>>>(bias, out);
}